// round 1
// baseline (speedup 1.0000x reference)
#include <cuda_runtime.h>
#include <math.h>

#define NN 8192
#define DD 64
#define CC 100
#define TT 30

// ---- scratch (device globals: no allocation allowed) ----
__device__ float g_lp[CC * NN];      // lp[c][n]
__device__ float g_al[CC * TT];      // alpha = softplus(alpha')
__device__ float g_be[CC * TT];      // beta  = softplus(beta') - alpha
__device__ float g_n0[CC * TT];      // ||z0[c,t]||^2

typedef unsigned long long u64;

// ---- packed f32x2 helpers (sm_103a) ----
__device__ __forceinline__ u64 pk2(float lo, float hi) {
    u64 r; asm("mov.b64 %0, {%1, %2};" : "=l"(r) : "f"(lo), "f"(hi)); return r;
}
__device__ __forceinline__ float2 upk2(u64 v) {
    float2 f; asm("mov.b64 {%0, %1}, %2;" : "=f"(f.x), "=f"(f.y) : "l"(v)); return f;
}
__device__ __forceinline__ u64 fma2(u64 a, u64 b, u64 c) {
    u64 d; asm("fma.rn.f32x2 %0, %1, %2, %3;" : "=l"(d) : "l"(a), "l"(b), "l"(c)); return d;
}
__device__ __forceinline__ u64 add2(u64 a, u64 b) {
    u64 d; asm("add.rn.f32x2 %0, %1, %2;" : "=l"(d) : "l"(a), "l"(b)); return d;
}

// ---- precompute per-(c,t) flow params ----
__global__ void prep_kernel(const float* __restrict__ z0,
                            const float* __restrict__ ap,
                            const float* __restrict__ bp) {
    int i = blockIdx.x * blockDim.x + threadIdx.x;
    if (i >= CC * TT) return;
    float a  = log1pf(expf(ap[i]));
    float be = log1pf(expf(bp[i])) - a;
    const float* z = z0 + (size_t)i * DD;
    float n0 = 0.f;
    #pragma unroll 8
    for (int d = 0; d < DD; ++d) n0 = fmaf(z[d], z[d], n0);
    g_al[i] = a; g_be[i] = be; g_n0[i] = n0;
}

// ---- main flow kernel: thread = (sample, class) chain ----
// grid: (N/128, C), block: 128
__global__ void __launch_bounds__(128, 4) flow_kernel(const float* __restrict__ x,
                                                      const float* __restrict__ z0g) {
    __shared__ __align__(16) float sz0[TT * DD];     // 7680 B
    __shared__ __align__(16) float sx[128 * 68];     // pitch 68 -> conflict-free row reads
    __shared__ float sal[TT], sbe[TT], sn0[TT];

    const int tid = threadIdx.x;
    const int c = blockIdx.y;
    const int nbase = blockIdx.x * 128;

    // stage z0[c] (coalesced)
    {
        const float4* gz = (const float4*)(z0g + (size_t)c * TT * DD);
        float4* sz = (float4*)sz0;
        #pragma unroll
        for (int i = tid; i < TT * DD / 4; i += 128) sz[i] = gz[i];
    }
    if (tid < TT) {
        sal[tid] = g_al[c * TT + tid];
        sbe[tid] = g_be[c * TT + tid];
        sn0[tid] = g_n0[c * TT + tid];
    }
    // stage x tile (coalesced), pitch 17 float4 per row
    {
        const float4* gx = (const float4*)(x + (size_t)nbase * DD);
        float4* sx4 = (float4*)sx;
        #pragma unroll
        for (int i = tid; i < 128 * 16; i += 128) {
            int r = i >> 4, col = i & 15;
            sx4[r * 17 + col] = gx[i];
        }
    }
    __syncthreads();

    // init z from own row
    u64 z[32];
    {
        const ulonglong2* xr = (const ulonglong2*)(sx + tid * 68);
        #pragma unroll
        for (int j = 0; j < 16; ++j) {
            ulonglong2 v = xr[j];
            z[2 * j] = v.x; z[2 * j + 1] = v.y;
        }
    }
    // q = ||z||^2
    float q;
    {
        u64 a0 = 0ull, a1 = 0ull, a2 = 0ull, a3 = 0ull;
        #pragma unroll
        for (int j = 0; j < 32; j += 4) {
            a0 = fma2(z[j],     z[j],     a0);
            a1 = fma2(z[j + 1], z[j + 1], a1);
            a2 = fma2(z[j + 2], z[j + 2], a2);
            a3 = fma2(z[j + 3], z[j + 3], a3);
        }
        float2 f = upk2(add2(add2(a0, a1), add2(a2, a3)));
        q = f.x + f.y;
    }

    float ld = 0.f;
    const ulonglong2* z0v = (const ulonglong2*)sz0;

    #pragma unroll 1
    for (int t = 0; t < TT; ++t) {
        const ulonglong2* zp = z0v + t * 16;
        // s = z . z0[t]
        u64 a0 = 0ull, a1 = 0ull, a2 = 0ull, a3 = 0ull;
        #pragma unroll
        for (int j = 0; j < 16; j += 2) {
            ulonglong2 v0 = zp[j];
            ulonglong2 v1 = zp[j + 1];
            a0 = fma2(z[2 * j],     v0.x, a0);
            a1 = fma2(z[2 * j + 1], v0.y, a1);
            a2 = fma2(z[2 * j + 2], v1.x, a2);
            a3 = fma2(z[2 * j + 3], v1.y, a3);
        }
        float2 sp = upk2(add2(add2(a0, a1), add2(a2, a3)));
        float s = sp.x + sp.y;

        float al = sal[t], be = sbe[t], nn = sn0[t];
        float r2 = fmaf(-2.f, s, q) + nn;             // ||z - z0||^2
        r2 = fmaxf(r2, 1e-20f);
        float rin = rsqrtf(r2);
        float r = r2 * rin;
        float h = __fdividef(1.f, al + r);
        float bh = be * h;
        float opbh = 1.f + bh;
        float t2 = opbh - bh * h * r;                 // 1 + bh(1 - h r)
        ld += 63.f * __logf(opbh) + __logf(t2);
        // ||z'||^2 = q + 2 bh (q - s) + bh^2 r^2
        q = fmaf(bh * bh, r2, fmaf(2.f * bh, q - s, q));

        // z' = (1+bh) z - bh z0
        u64 bp2 = pk2(bh, bh);
        u64 nb2 = pk2(-bh, -bh);
        #pragma unroll
        for (int j = 0; j < 16; ++j) {
            ulonglong2 v = zp[j];
            u64 t0 = fma2(bp2, z[2 * j],     z[2 * j]);
            u64 t1 = fma2(bp2, z[2 * j + 1], z[2 * j + 1]);
            z[2 * j]     = fma2(nb2, v.x, t0);
            z[2 * j + 1] = fma2(nb2, v.y, t1);
        }
    }

    // lp = -0.5*(D log 2pi + ||z||^2) + ld
    float lp = ld - 0.5f * q - 58.8120661251f;
    g_lp[(size_t)c * NN + nbase + tid] = lp;
}

// ---- epilogue: thread = sample ----
__global__ void __launch_bounds__(128) out_kernel(const float* __restrict__ x,
                                                  const int* __restrict__ labels,
                                                  const float* __restrict__ freq,
                                                  const float* __restrict__ W,
                                                  const float* __restrict__ b,
                                                  float* __restrict__ out) {
    __shared__ float sW[DD * CC];
    __shared__ float sb[CC], slf[CC];
    const int tid = threadIdx.x;
    for (int i = tid; i < DD * CC; i += 128) sW[i] = W[i];
    for (int i = tid; i < CC; i += 128) { sb[i] = b[i]; slf[i] = __logf(freq[i]); }
    __syncthreads();

    const int n = blockIdx.x * 128 + tid;
    float xr[DD];
    {
        const float4* xp = (const float4*)(x + (size_t)n * DD);
        #pragma unroll
        for (int j = 0; j < 16; ++j) {
            float4 v = __ldg(xp + j);
            xr[4 * j] = v.x; xr[4 * j + 1] = v.y; xr[4 * j + 2] = v.z; xr[4 * j + 3] = v.w;
        }
    }

    float logits[CC];
    float mlg = -1e30f, mlp = -1e30f;
    #pragma unroll 1
    for (int c = 0; c < CC; ++c) {
        float acc = sb[c];
        #pragma unroll
        for (int d = 0; d < DD; ++d) acc = fmaf(xr[d], sW[d * CC + c], acc);
        logits[c] = acc;
        mlg = fmaxf(mlg, acc);
        mlp = fmaxf(mlp, g_lp[(size_t)c * NN + n] + slf[c]);
    }
    float se = 0.f, sl = 0.f;
    #pragma unroll 1
    for (int c = 0; c < CC; ++c) {
        se += __expf(g_lp[(size_t)c * NN + n] + slf[c] - mlp);
        sl += __expf(logits[c] - mlg);
    }
    float marg = mlp + __logf(se);
    const float EVB = 80.992775903f;                 // 0.5*D*log(4*pi)
    float logev = fminf(marg + EVB, 10.f);
    float EoS = __expf(logev) / sl;                  // evidence / softmax denom

    float* o = out + (size_t)n * (CC + 1);
    #pragma unroll 1
    for (int c = 0; c < CC; ++c)
        o[c] = __logf(fmaf(EoS, __expf(logits[c] - mlg), 1.f));
    o[CC] = g_lp[(size_t)labels[n] * NN + n];
}

extern "C" void kernel_launch(void* const* d_in, const int* in_sizes, int n_in,
                              void* d_out, int out_size) {
    const float* x      = (const float*)d_in[0];
    const int*   labels = (const int*)d_in[1];
    const float* freq   = (const float*)d_in[2];
    const float* z0     = (const float*)d_in[3];
    const float* ap     = (const float*)d_in[4];
    const float* bp     = (const float*)d_in[5];
    const float* W      = (const float*)d_in[6];
    const float* b      = (const float*)d_in[7];
    float* out = (float*)d_out;

    prep_kernel<<<(CC * TT + 127) / 128, 128>>>(z0, ap, bp);
    dim3 grid(NN / 128, CC);
    flow_kernel<<<grid, 128>>>(x, z0);
    out_kernel<<<NN / 128, 128>>>(x, labels, freq, W, b, out);
}

// round 2
// speedup vs baseline: 1.8474x; 1.8474x over previous
#include <cuda_runtime.h>
#include <math.h>

#define NN 8192
#define DD 64
#define CC 100
#define TT 30

// ---- device-global scratch ----
__device__ float g_lp[CC * NN];        // lp[c][n]
__device__ float g_al[CC * TT];        // softplus(alpha')
__device__ float g_be[CC * TT];        // softplus(beta') - alpha
__device__ float g_n0[CC * TT];        // ||z0||^2
__device__ float g_G[CC * TT * 32];    // Gram rows, pitch 32: G[c][t][i] = z0_t . z0_i (i<t)

typedef unsigned long long u64;

// ---- packed f32x2 helpers (sm_103a FFMA2) ----
__device__ __forceinline__ float2 upk2(u64 v) {
    float2 f; asm("mov.b64 {%0, %1}, %2;" : "=f"(f.x), "=f"(f.y) : "l"(v)); return f;
}
__device__ __forceinline__ u64 fma2(u64 a, u64 b, u64 c) {
    u64 d; asm("fma.rn.f32x2 %0, %1, %2, %3;" : "=l"(d) : "l"(a), "l"(b), "l"(c)); return d;
}
__device__ __forceinline__ u64 add2(u64 a, u64 b) {
    u64 d; asm("add.rn.f32x2 %0, %1, %2;" : "=l"(d) : "l"(a), "l"(b)); return d;
}

// ---- prep: per-class flow params + Gram matrix ----
__global__ void __launch_bounds__(128) prep_kernel(const float* __restrict__ z0,
                                                   const float* __restrict__ ap,
                                                   const float* __restrict__ bp) {
    __shared__ __align__(16) float sz[TT * DD];
    const int tid = threadIdx.x;
    const int c = blockIdx.x;
    {
        const float4* gz = (const float4*)(z0 + (size_t)c * TT * DD);
        float4* s4 = (float4*)sz;
        for (int i = tid; i < TT * DD / 4; i += 128) s4[i] = gz[i];
    }
    __syncthreads();
    if (tid < TT) {
        float a = log1pf(__expf(ap[c * TT + tid]));
        float be = log1pf(__expf(bp[c * TT + tid])) - a;
        g_al[c * TT + tid] = a;
        g_be[c * TT + tid] = be;
    }
    for (int k = tid; k < TT * TT; k += 128) {
        int t = k / TT, i = k % TT;
        if (i > t) continue;
        const float* za = sz + t * DD;
        const float* zb = sz + i * DD;
        float acc = 0.f;
        #pragma unroll 16
        for (int d = 0; d < DD; ++d) acc = fmaf(za[d], zb[d], acc);
        if (i == t) g_n0[c * TT + t] = acc;
        else        g_G[(size_t)c * TT * 32 + t * 32 + i] = acc;
    }
}

// ---- flow: thread = (sample, class) chain in coefficient space ----
// grid (N/128, C), block 128
__global__ void __launch_bounds__(128, 4) flow_kernel(const float* __restrict__ x,
                                                      const float* __restrict__ z0g) {
    __shared__ __align__(16) float sz0[TT * DD];      // 7680 B
    __shared__ __align__(16) float sG[TT * 32];       // 3840 B
    __shared__ float sal[TT], sbe[TT], sn0[TT];
    __shared__ __align__(16) float buf[128 * 68];     // 34816 B: x tile, then reused for p

    const int tid = threadIdx.x;
    const int c = blockIdx.y;
    const int nbase = blockIdx.x * 128;

    {   // stage z0[c]
        const float4* gz = (const float4*)(z0g + (size_t)c * TT * DD);
        float4* s4 = (float4*)sz0;
        #pragma unroll
        for (int i = tid; i < 480; i += 128) s4[i] = gz[i];
    }
    {   // stage Gram rows
        const float4* gg = (const float4*)(g_G + (size_t)c * TT * 32);
        float4* s4 = (float4*)sG;
        #pragma unroll
        for (int i = tid; i < 240; i += 128) s4[i] = gg[i];
    }
    if (tid < TT) {
        sal[tid] = g_al[c * TT + tid];
        sbe[tid] = g_be[c * TT + tid];
        sn0[tid] = g_n0[c * TT + tid];
    }
    {   // stage x tile coalesced, pitch 17 float4
        const float4* gx = (const float4*)(x + (size_t)nbase * DD);
        float4* s4 = (float4*)buf;
        #pragma unroll
        for (int i = tid; i < 128 * 16; i += 128) {
            int r = i >> 4, col = i & 15;
            s4[r * 17 + col] = gx[i];
        }
    }
    __syncthreads();

    // own x row -> packed regs; q0 = ||x||^2
    u64 xv[32];
    {
        const ulonglong2* xr = (const ulonglong2*)(buf + tid * 68);
        #pragma unroll
        for (int j = 0; j < 16; ++j) {
            ulonglong2 v = xr[j];
            xv[2 * j] = v.x; xv[2 * j + 1] = v.y;
        }
    }
    float q;
    {
        u64 a0 = 0ull, a1 = 0ull, a2 = 0ull, a3 = 0ull;
        #pragma unroll
        for (int j = 0; j < 32; j += 4) {
            a0 = fma2(xv[j],     xv[j],     a0);
            a1 = fma2(xv[j + 1], xv[j + 1], a1);
            a2 = fma2(xv[j + 2], xv[j + 2], a2);
            a3 = fma2(xv[j + 3], xv[j + 3], a3);
        }
        float2 f = upk2(add2(add2(a0, a1), add2(a2, a3)));
        q = f.x + f.y;
    }
    __syncthreads();   // everyone done reading x tile; buf becomes p storage

    // P phase: p[t] = x . z0_t  (independent dots, ILP-rich)
    float* sp = buf;
    #pragma unroll 1
    for (int t = 0; t < TT; ++t) {
        const ulonglong2* zp = (const ulonglong2*)(sz0 + t * DD);
        u64 a0 = 0ull, a1 = 0ull, a2 = 0ull, a3 = 0ull;
        #pragma unroll
        for (int j = 0; j < 16; j += 2) {
            ulonglong2 v0 = zp[j];
            ulonglong2 v1 = zp[j + 1];
            a0 = fma2(xv[2 * j],     v0.x, a0);
            a1 = fma2(xv[2 * j + 1], v0.y, a1);
            a2 = fma2(xv[2 * j + 2], v1.x, a2);
            a3 = fma2(xv[2 * j + 3], v1.y, a3);
        }
        float2 f = upk2(add2(add2(a0, a1), add2(a2, a3)));
        sp[t * 128 + tid] = f.x + f.y;
    }

    // scalar chain in coefficient space
    float w[TT];
    float ld = 0.f, g = 1.f;
    #pragma unroll
    for (int t = 0; t < TT; ++t) {
        float acc0 = sp[t * 128 + tid];
        float acc1 = 0.f;
        const float* Gr = sG + t * 32;
        int i = 0;
        #pragma unroll
        for (; i + 4 <= t; i += 4) {
            float4 g4 = *(const float4*)(Gr + i);
            acc0 = fmaf(w[i],     g4.x, acc0);
            acc1 = fmaf(w[i + 1], g4.y, acc1);
            acc0 = fmaf(w[i + 2], g4.z, acc0);
            acc1 = fmaf(w[i + 3], g4.w, acc1);
        }
        #pragma unroll
        for (; i < t; ++i) acc0 = fmaf(w[i], Gr[i], acc0);
        float s = g * (acc0 + acc1);

        float al = sal[t], be = sbe[t], nn = sn0[t];
        float r2 = fmaf(-2.f, s, q) + nn;
        r2 = fmaxf(r2, 1e-20f);
        float rin = rsqrtf(r2);
        float r = r2 * rin;
        float h = __fdividef(1.f, al + r);
        float bh = be * h;
        float opbh = 1.f + bh;
        float t2 = opbh - bh * h * r;
        ld += 63.f * __logf(opbh) + __logf(t2);
        q = fmaf(bh * bh, r2, fmaf(2.f * bh, q - s, q));
        float g2 = g * opbh;
        w[t] = -__fdividef(bh, g2);
        g = g2;
    }

    g_lp[(size_t)c * NN + nbase + tid] = ld - 0.5f * q - 58.8120661251f;
}

// ---- epilogue: warp = sample, lane handles classes lane, lane+32, ... ----
__global__ void __launch_bounds__(256) out_kernel(const float* __restrict__ x,
                                                  const int* __restrict__ labels,
                                                  const float* __restrict__ freq,
                                                  const float* __restrict__ W,
                                                  const float* __restrict__ b,
                                                  float* __restrict__ out) {
    __shared__ __align__(16) float sWt[CC * 68];   // W transposed, pitch 68
    __shared__ __align__(16) float sxr[8 * 68];
    __shared__ float sb[CC], slf[CC];
    const int tid = threadIdx.x;
    for (int i = tid; i < DD * CC; i += 256) {
        int d = i / CC, cc = i % CC;
        sWt[cc * 68 + d] = W[i];
    }
    for (int i = tid; i < CC; i += 256) { sb[i] = b[i]; slf[i] = __logf(freq[i]); }

    const int wid = tid >> 5, lane = tid & 31;
    const int n = blockIdx.x * 8 + wid;
    {
        const float2* xp = (const float2*)(x + (size_t)n * DD);
        ((float2*)(sxr + wid * 68))[lane] = xp[lane];
    }
    __syncthreads();

    u64 xv[32];
    {
        const ulonglong2* xr = (const ulonglong2*)(sxr + wid * 68);
        #pragma unroll
        for (int j = 0; j < 16; ++j) {
            ulonglong2 v = xr[j];
            xv[2 * j] = v.x; xv[2 * j + 1] = v.y;
        }
    }

    float lg[4], lq[4];
    float mlg = -1e30f, mlp = -1e30f;
    #pragma unroll
    for (int k = 0; k < 4; ++k) {
        int cc = lane + 32 * k;
        if (cc < CC) {
            const ulonglong2* wr = (const ulonglong2*)(sWt + cc * 68);
            u64 a0 = 0ull, a1 = 0ull;
            #pragma unroll
            for (int j = 0; j < 16; ++j) {
                ulonglong2 v = wr[j];
                a0 = fma2(xv[2 * j],     v.x, a0);
                a1 = fma2(xv[2 * j + 1], v.y, a1);
            }
            float2 f = upk2(add2(a0, a1));
            lg[k] = f.x + f.y + sb[cc];
            lq[k] = g_lp[(size_t)cc * NN + n] + slf[cc];
        } else {
            lg[k] = -1e30f; lq[k] = -1e30f;
        }
        mlg = fmaxf(mlg, lg[k]);
        mlp = fmaxf(mlp, lq[k]);
    }
    #pragma unroll
    for (int o = 16; o; o >>= 1) {
        mlg = fmaxf(mlg, __shfl_xor_sync(0xffffffffu, mlg, o));
        mlp = fmaxf(mlp, __shfl_xor_sync(0xffffffffu, mlp, o));
    }
    float se = 0.f, sl = 0.f;
    #pragma unroll
    for (int k = 0; k < 4; ++k) {
        if (lane + 32 * k < CC) {
            se += __expf(lq[k] - mlp);
            sl += __expf(lg[k] - mlg);
        }
    }
    #pragma unroll
    for (int o = 16; o; o >>= 1) {
        se += __shfl_xor_sync(0xffffffffu, se, o);
        sl += __shfl_xor_sync(0xffffffffu, sl, o);
    }
    float marg = mlp + __logf(se);
    float logev = fminf(marg + 80.992775903f, 10.f);     // + 0.5*D*log(4pi)
    float E = __expf(logev) / sl;                        // evidence / softmax denom

    float* o = out + (size_t)n * (CC + 1);
    #pragma unroll
    for (int k = 0; k < 4; ++k) {
        int cc = lane + 32 * k;
        if (cc < CC)
            o[cc] = __logf(fmaf(E, __expf(lg[k] - mlg), 1.f));
    }
    if (lane == 0)
        o[CC] = g_lp[(size_t)labels[n] * NN + n];
}

extern "C" void kernel_launch(void* const* d_in, const int* in_sizes, int n_in,
                              void* d_out, int out_size) {
    const float* x      = (const float*)d_in[0];
    const int*   labels = (const int*)d_in[1];
    const float* freq   = (const float*)d_in[2];
    const float* z0     = (const float*)d_in[3];
    const float* ap     = (const float*)d_in[4];
    const float* bp     = (const float*)d_in[5];
    const float* W      = (const float*)d_in[6];
    const float* b      = (const float*)d_in[7];
    float* out = (float*)d_out;

    prep_kernel<<<CC, 128>>>(z0, ap, bp);
    dim3 grid(NN / 128, CC);
    flow_kernel<<<grid, 128>>>(x, z0);
    out_kernel<<<NN / 8, 256>>>(x, labels, freq, W, b, out);
}